// round 2
// baseline (speedup 1.0000x reference)
#include <cuda_runtime.h>
#include <cuda_bf16.h>
#include <cstdint>

#define BATCH 4
#define NPTS 8192
#define NSAMP 2048
#define KNN_K 16
#define INDIM 64
#define OUTDIM 128
#define CIN 67

typedef unsigned long long ull;

__device__ int g_knn[BATCH * NSAMP * KNN_K];

// ---------- packed f32x2 helpers (per-lane bit-identical to scalar FFMA/FMUL/FADD) ----------
__device__ __forceinline__ ull f2pk(float lo, float hi) {
    ull r; asm("mov.b64 %0, {%1,%2};" : "=l"(r) : "f"(lo), "f"(hi)); return r;
}
__device__ __forceinline__ void f2up(ull v, float& lo, float& hi) {
    asm("mov.b64 {%0,%1}, %2;" : "=f"(lo), "=f"(hi) : "l"(v));
}
__device__ __forceinline__ ull f2add(ull a, ull b) {
    ull r; asm("add.rn.f32x2 %0, %1, %2;" : "=l"(r) : "l"(a), "l"(b)); return r;
}
__device__ __forceinline__ ull f2mul(ull a, ull b) {
    ull r; asm("mul.rn.f32x2 %0, %1, %2;" : "=l"(r) : "l"(a), "l"(b)); return r;
}
__device__ __forceinline__ ull f2fma(ull a, ull b, ull c) {
    ull r; asm("fma.rn.f32x2 %0, %1, %2, %3;" : "=l"(r) : "l"(a), "l"(b), "l"(c)); return r;
}

// ============================================================================
// Kernel 1: farthest point sampling. One block per batch, 512 threads,
// 16 points per thread held in registers as 8 f32x2 pairs.
// ============================================================================
#define FPS_T 512
#define FPS_SMEM (3 * NPTS * 4)

__global__ __launch_bounds__(FPS_T, 1)
void fps_kernel(const float* __restrict__ xyz, float* __restrict__ oxyz) {
    extern __shared__ float sm[];
    float* sx = sm;
    float* sy = sm + NPTS;
    float* sz = sm + 2 * NPTS;
    __shared__ float rv[16];
    __shared__ int rp[16];
    __shared__ int scur;

    const int b = blockIdx.x;
    const int t = threadIdx.x;
    const float* bx = xyz + (size_t)b * NPTS * 3;

    for (int i = t; i < NPTS; i += FPS_T) {
        sx[i] = bx[i * 3 + 0];
        sy[i] = bx[i * 3 + 1];
        sz[i] = bx[i * 3 + 2];
    }
    __syncthreads();

    ull px2[8], py2[8], pz2[8];
    float pd[16];
#pragma unroll
    for (int m = 0; m < 8; m++) {
        int i0 = (2 * m) * FPS_T + t;
        int i1 = i0 + FPS_T;
        px2[m] = f2pk(sx[i0], sx[i1]);
        py2[m] = f2pk(sy[i0], sy[i1]);
        pz2[m] = f2pk(sz[i0], sz[i1]);
        pd[2 * m] = 1e10f;
        pd[2 * m + 1] = 1e10f;
    }
    if (t == 0) {
        float* o = oxyz + (size_t)b * NSAMP * 3;
        o[0] = sx[0]; o[1] = sy[0]; o[2] = sz[0];
    }

    int cur = 0;
    for (int s = 1; s < NSAMP; s++) {
        float cx = sx[cur], cy = sy[cur], cz = sz[cur];
        ull ncx = f2pk(-cx, -cx);
        ull ncy = f2pk(-cy, -cy);
        ull ncz = f2pk(-cz, -cz);
        float bv = -1.0f;
        int bj = 0;
#pragma unroll
        for (int m = 0; m < 8; m++) {
            ull dx = f2add(px2[m], ncx);
            ull dy = f2add(py2[m], ncy);
            ull dz = f2add(pz2[m], ncz);
            ull dd = f2mul(dx, dx);
            dd = f2fma(dy, dy, dd);
            dd = f2fma(dz, dz, dd);
            float d0, d1;
            f2up(dd, d0, d1);
            float n0 = fminf(pd[2 * m], d0);
            pd[2 * m] = n0;
            float n1 = fminf(pd[2 * m + 1], d1);
            pd[2 * m + 1] = n1;
            if (n0 > bv) { bv = n0; bj = 2 * m; }
            if (n1 > bv) { bv = n1; bj = 2 * m + 1; }
        }
        int bi = bj * FPS_T + t;

        // warp reduce (argmax, ties -> smallest index, matching jnp.argmax)
#pragma unroll
        for (int off = 16; off; off >>= 1) {
            float v2 = __shfl_down_sync(0xffffffffu, bv, off);
            int i2 = __shfl_down_sync(0xffffffffu, bi, off);
            if (v2 > bv || (v2 == bv && i2 < bi)) { bv = v2; bi = i2; }
        }
        if ((t & 31) == 0) { rv[t >> 5] = bv; rp[t >> 5] = bi; }
        __syncthreads();
        if (t < 32) {
            float v = (t < 16) ? rv[t] : -1.0f;
            int i = (t < 16) ? rp[t] : 0x7fffffff;
#pragma unroll
            for (int off = 8; off; off >>= 1) {
                float v2 = __shfl_down_sync(0xffffffffu, v, off);
                int i2 = __shfl_down_sync(0xffffffffu, i, off);
                if (v2 > v || (v2 == v && i2 < i)) { v = v2; i = i2; }
            }
            if (t == 0) {
                scur = i;
                float* o = oxyz + ((size_t)b * NSAMP + s) * 3;
                o[0] = sx[i]; o[1] = sy[i]; o[2] = sz[i];
            }
        }
        __syncthreads();
        cur = scur;
    }
}

// ============================================================================
// Kernel 2: KNN (k=16). 128 blocks x 256 threads. 64 queries/block,
// 4 threads per query scan interleaved point slices; register-resident
// descending-sorted top-16; lexicographic pair merge.
// ============================================================================
#define KTS 1024

__global__ __launch_bounds__(256, 1)
void knn_kernel(const float* __restrict__ xyz, const float* __restrict__ qxyz) {
    __shared__ float stx[KTS], sty[KTS], stz[KTS], st2[KTS];
    __shared__ float smd[64 * 48];
    __shared__ int smi[64 * 48];

    const int t = threadIdx.x;
    const int blk = blockIdx.x;
    const int b = blk >> 5;
    const int q0 = (blk & 31) * 64;
    const int ql = t >> 2;
    const int par = t & 3;
    const int q = q0 + ql;

    const float* qp = qxyz + ((size_t)b * NSAMP + q) * 3;
    const float qx = qp[0], qy = qp[1], qz = qp[2];
    const float q2 = qx * qx + qy * qy + qz * qz;

    float dk[16];
    int ik[16];
#pragma unroll
    for (int i = 0; i < 16; i++) { dk[i] = 3.4e38f; ik[i] = 0; }

    const float* bx = xyz + (size_t)b * NPTS * 3;
    for (int tile = 0; tile < NPTS / KTS; tile++) {
        __syncthreads();
        for (int i = t; i < KTS; i += 256) {
            int p = tile * KTS + i;
            float x = bx[p * 3 + 0], y = bx[p * 3 + 1], z = bx[p * 3 + 2];
            stx[i] = x; sty[i] = y; stz[i] = z;
            st2[i] = x * x + y * y + z * z;
        }
        __syncthreads();
        for (int j = par; j < KTS; j += 4) {
            float dot = qx * stx[j] + qy * sty[j] + qz * stz[j];
            float d = q2 + st2[j] - 2.0f * dot;   // matmul form, matches reference
            if (d < dk[0]) {
                int idx = tile * KTS + j;
                dk[0] = d; ik[0] = idx;
#pragma unroll
                for (int r = 0; r < 15; r++) {
                    if (dk[r] < dk[r + 1]) {
                        float td = dk[r]; dk[r] = dk[r + 1]; dk[r + 1] = td;
                        int ti = ik[r]; ik[r] = ik[r + 1]; ik[r + 1] = ti;
                    }
                }
            }
        }
    }
    __syncthreads();

    if (par) {
        int base = ql * 48 + (par - 1) * 16;
#pragma unroll
        for (int i = 0; i < 16; i++) { smd[base + i] = dk[i]; smi[base + i] = ik[i]; }
    }
    __syncthreads();

    if (par == 0) {
        for (int e = 0; e < 48; e++) {
            float d = smd[ql * 48 + e];
            int idx = smi[ql * 48 + e];
            if (d < dk[0] || (d == dk[0] && idx < ik[0])) {
                dk[0] = d; ik[0] = idx;
#pragma unroll
                for (int r = 0; r < 15; r++) {
                    bool sw = (dk[r] < dk[r + 1]) ||
                              (dk[r] == dk[r + 1] && ik[r] < ik[r + 1]);
                    if (sw) {
                        float td = dk[r]; dk[r] = dk[r + 1]; dk[r + 1] = td;
                        int ti = ik[r]; ik[r] = ik[r + 1]; ik[r + 1] = ti;
                    }
                }
            }
        }
        int* dst = g_knn + (((size_t)b * NSAMP + q) << 4);
#pragma unroll
        for (int i = 0; i < 16; i++) dst[i] = ik[i];
    }
}

// ============================================================================
// Kernel 3: fused gather + MLP(67->128, relu, 128->128) + maxpool(K) + LN.
// 1024 blocks x 256 threads; 8 queries (=128 neighbor rows) per block.
// All operands staged in shared (~210KB); threads compute 8x8 register tiles.
// G rows stored feat-first (cols 0..63 = feat, 64..66 = xyz diff) so float4
// gathers stay aligned; W1 rows are permuted to match at load time.
// ============================================================================
#define MLP_SMEM_FLOATS (8576 + 16384 + 8704 + 16896 + 2048 + 1024)
#define MLP_SMEM (MLP_SMEM_FLOATS * 4)

__global__ __launch_bounds__(256, 1)
void mlp_kernel(const float* __restrict__ xyz, const float* __restrict__ feat,
                const float* __restrict__ newxyz,
                const float* __restrict__ W1, const float* __restrict__ b1,
                const float* __restrict__ W2, const float* __restrict__ b2,
                const float* __restrict__ lg, const float* __restrict__ lb,
                float* __restrict__ outf) {
    extern __shared__ float sm[];
    float* W1s = sm;            // 67*128 (rows permuted: feat rows 0..63, xyz rows 64..66)
    float* W2s = W1s + 8576;    // 128*128
    float* Gs  = W2s + 16384;   // 128 x 68 (pad)
    float* Hs  = Gs + 8704;     // 128 x 132 (pad)
    float* Ps  = Hs + 16896;    // 16 x 128 partial pool
    float* Qs  = Ps + 2048;     // 8 x 128 pooled

    const int t = threadIdx.x;
    const int blk = blockIdx.x;
    const int b = blk >> 8;
    const int q0 = (blk & 255) * 8;

    // load W1 (permute input rows: src row sr<3 (xyz) -> 64+sr, else sr-3)
    for (int e = t; e < CIN * OUTDIM; e += 256) {
        int sr = e >> 7, c = e & 127;
        int dr = (sr < 3) ? (64 + sr) : (sr - 3);
        W1s[dr * 128 + c] = W1[e];
    }
    // load W2
    {
        const float4* src = (const float4*)W2;
        float4* dst = (float4*)W2s;
        for (int e = t; e < 4096; e += 256) dst[e] = src[e];
    }
    // gather grouped rows: 2 threads per row
    {
        int r = t >> 1, half = t & 1;
        int qlq = r >> 4, kk = r & 15;
        int q = q0 + qlq;
        int nidx = g_knn[(((size_t)b * NSAMP + q) << 4) + kk];
        const float* frow = feat + ((size_t)b * NPTS + nidx) * INDIM + half * 32;
        float* grow = Gs + r * 68;
#pragma unroll
        for (int i = 0; i < 8; i++) {
            float4 v = *(const float4*)(frow + i * 4);
            *(float4*)(grow + half * 32 + i * 4) = v;
        }
        if (half == 0) {
            const float* prow = xyz + ((size_t)b * NPTS + nidx) * 3;
            const float* crow = newxyz + ((size_t)b * NSAMP + q) * 3;
            grow[64] = prow[0] - crow[0];
            grow[65] = prow[1] - crow[1];
            grow[66] = prow[2] - crow[2];
        }
    }
    __syncthreads();

    const int tx = t & 15, ty = t >> 4;
    const int c0 = tx * 8, r0 = ty * 8;

    float acc[8][8];
    {
        float bb[8];
#pragma unroll
        for (int j = 0; j < 8; j++) bb[j] = __ldg(b1 + c0 + j);
#pragma unroll
        for (int i = 0; i < 8; i++)
#pragma unroll
            for (int j = 0; j < 8; j++) acc[i][j] = bb[j];
    }
    for (int k = 0; k < CIN; k++) {
        float w[8], g[8];
        float4 w0 = *(const float4*)(W1s + k * 128 + c0);
        float4 w1 = *(const float4*)(W1s + k * 128 + c0 + 4);
        w[0] = w0.x; w[1] = w0.y; w[2] = w0.z; w[3] = w0.w;
        w[4] = w1.x; w[5] = w1.y; w[6] = w1.z; w[7] = w1.w;
#pragma unroll
        for (int i = 0; i < 8; i++) g[i] = Gs[(r0 + i) * 68 + k];
#pragma unroll
        for (int i = 0; i < 8; i++)
#pragma unroll
            for (int j = 0; j < 8; j++) acc[i][j] += g[i] * w[j];
    }
    // relu + store H
#pragma unroll
    for (int i = 0; i < 8; i++) {
        float4 v0, v1;
        v0.x = fmaxf(acc[i][0], 0.f); v0.y = fmaxf(acc[i][1], 0.f);
        v0.z = fmaxf(acc[i][2], 0.f); v0.w = fmaxf(acc[i][3], 0.f);
        v1.x = fmaxf(acc[i][4], 0.f); v1.y = fmaxf(acc[i][5], 0.f);
        v1.z = fmaxf(acc[i][6], 0.f); v1.w = fmaxf(acc[i][7], 0.f);
        *(float4*)(Hs + (r0 + i) * 132 + c0) = v0;
        *(float4*)(Hs + (r0 + i) * 132 + c0 + 4) = v1;
    }
    __syncthreads();

    {
        float bb[8];
#pragma unroll
        for (int j = 0; j < 8; j++) bb[j] = __ldg(b2 + c0 + j);
#pragma unroll
        for (int i = 0; i < 8; i++)
#pragma unroll
            for (int j = 0; j < 8; j++) acc[i][j] = bb[j];
    }
    for (int k = 0; k < OUTDIM; k++) {
        float w[8], h[8];
        float4 w0 = *(const float4*)(W2s + k * 128 + c0);
        float4 w1 = *(const float4*)(W2s + k * 128 + c0 + 4);
        w[0] = w0.x; w[1] = w0.y; w[2] = w0.z; w[3] = w0.w;
        w[4] = w1.x; w[5] = w1.y; w[6] = w1.z; w[7] = w1.w;
#pragma unroll
        for (int i = 0; i < 8; i++) h[i] = Hs[(r0 + i) * 132 + k];
#pragma unroll
        for (int i = 0; i < 8; i++)
#pragma unroll
            for (int j = 0; j < 8; j++) acc[i][j] += h[i] * w[j];
    }
    // pool over this thread's 8 rows (all within one query half)
    {
        float m[8];
#pragma unroll
        for (int j = 0; j < 8; j++) {
            float v = acc[0][j];
#pragma unroll
            for (int i = 1; i < 8; i++) v = fmaxf(v, acc[i][j]);
            m[j] = v;
        }
        float4 v0, v1;
        v0.x = m[0]; v0.y = m[1]; v0.z = m[2]; v0.w = m[3];
        v1.x = m[4]; v1.y = m[5]; v1.z = m[6]; v1.w = m[7];
        *(float4*)(Ps + ty * 128 + c0) = v0;
        *(float4*)(Ps + ty * 128 + c0 + 4) = v1;
    }
    __syncthreads();
    for (int e = t; e < 1024; e += 256) {
        int q = e >> 7, c = e & 127;
        Qs[e] = fmaxf(Ps[(2 * q) * 128 + c], Ps[(2 * q + 1) * 128 + c]);
    }
    __syncthreads();

    // layernorm: warp w handles query w
    {
        int w = t >> 5, l = t & 31;
        float4 v = *(const float4*)(Qs + w * 128 + l * 4);
        float sum = v.x + v.y + v.z + v.w;
        float sq = fmaf(v.x, v.x, fmaf(v.y, v.y, fmaf(v.z, v.z, v.w * v.w)));
#pragma unroll
        for (int off = 16; off; off >>= 1) {
            sum += __shfl_xor_sync(0xffffffffu, sum, off);
            sq += __shfl_xor_sync(0xffffffffu, sq, off);
        }
        float mu = sum * (1.0f / 128.0f);
        float var = sq * (1.0f / 128.0f) - mu * mu;
        float rs = rsqrtf(var + 1e-5f);
        int qg = q0 + w;
        int c = l * 4;
        float4 o;
        o.x = (v.x - mu) * rs * __ldg(lg + c + 0) + __ldg(lb + c + 0);
        o.y = (v.y - mu) * rs * __ldg(lg + c + 1) + __ldg(lb + c + 1);
        o.z = (v.z - mu) * rs * __ldg(lg + c + 2) + __ldg(lb + c + 2);
        o.w = (v.w - mu) * rs * __ldg(lg + c + 3) + __ldg(lb + c + 3);
        *(float4*)(outf + (((size_t)b * NSAMP + qg) << 7) + c) = o;
    }
}

// ============================================================================
extern "C" void kernel_launch(void* const* d_in, const int* in_sizes, int n_in,
                              void* d_out, int out_size) {
    const float* xyz  = (const float*)d_in[0];
    const float* feat = (const float*)d_in[1];
    const float* W1   = (const float*)d_in[2];
    const float* b1   = (const float*)d_in[3];
    const float* W2   = (const float*)d_in[4];
    const float* b2   = (const float*)d_in[5];
    const float* lg   = (const float*)d_in[6];
    const float* lb   = (const float*)d_in[7];

    float* out = (float*)d_out;
    float* oxyz = out;                                  // (B, S, 3)
    float* ofeat = out + (size_t)BATCH * NSAMP * 3;     // (B, S, 128)

    cudaFuncSetAttribute(fps_kernel, cudaFuncAttributeMaxDynamicSharedMemorySize, FPS_SMEM);
    cudaFuncSetAttribute(mlp_kernel, cudaFuncAttributeMaxDynamicSharedMemorySize, MLP_SMEM);

    fps_kernel<<<BATCH, FPS_T, FPS_SMEM>>>(xyz, oxyz);
    knn_kernel<<<128, 256>>>(xyz, oxyz);
    mlp_kernel<<<1024, 256, MLP_SMEM>>>(xyz, feat, oxyz, W1, b1, W2, b2, lg, lb, ofeat);
}

// round 3
// speedup vs baseline: 1.1160x; 1.1160x over previous
#include <cuda_runtime.h>
#include <cuda_bf16.h>
#include <cstdint>

#define BATCH 4
#define NPTS 8192
#define NSAMP 2048
#define KNN_K 16
#define INDIM 64
#define OUTDIM 128
#define CIN 67
#define NBMX 704

__device__ int g_knn[BATCH * NSAMP * KNN_K];

// ============================================================================
// Kernel 1: bucketed exact farthest point sampling. One block per batch,
// 512 threads. Points counting-sorted into 8x8x8 cells, split into buckets
// of <=64 points with tight bboxes. Per iteration only buckets whose
// conservative (bit-exact monotone) lower bound beats their stale max get
// rescanned. Reductions use REDUX.SYNC (value-bits max + payload min).
// ============================================================================
#define FPS_T 512
#define FPS_SMEM 199232

__global__ __launch_bounds__(FPS_T, 1)
void fps_kernel(const float* __restrict__ xyz, float* __restrict__ oxyz) {
    extern __shared__ float sm[];
    float* sxs = sm;                       // 8192 sorted coords
    float* sys = sxs + NPTS;
    float* szs = sys + NPTS;
    float* pds = szs + NPTS;               // 8192 min-dists
    int*   opk = (int*)(pds + NPTS);       // 8192 payload (orig<<16)|pos
    float* blox = (float*)(opk + NPTS);    // bucket bboxes
    float* bloy = blox + NBMX;
    float* bloz = bloy + NBMX;
    float* bhix = bloz + NBMX;
    float* bhiy = bhix + NBMX;
    float* bhiz = bhiy + NBMX;
    float* bmaxv = bhiz + NBMX;            // bucket running max pd
    int* bpay   = (int*)(bmaxv + NBMX);    // bucket argmax payload
    int* bstart = bpay + NBMX;
    int* bcnt   = bstart + NBMX;
    int* act    = bcnt + NBMX;             // active bucket list
    int* cellCnt   = act + NBMX;           // 512
    int* cellStart = cellCnt + 512;        // 512
    unsigned* pv = (unsigned*)(cellStart + 512);  // 2x16 partial values
    int* pp = (int*)(pv + 32);                    // 2x16 partial payloads
    float* gbb = (float*)(pp + 32);        // lox,loy,loz,sclx,scly,sclz
    int* gnB   = (int*)(gbb + 8);
    int* gnAct = gnB + 1;

    const int b = blockIdx.x;
    const int t = threadIdx.x;
    const int wid = t >> 5;
    const int lane = t & 31;
    const float* bx = xyz + (size_t)b * NPTS * 3;

    // ---- P0: cloud bbox (warp partials), zero counters ----
    {
        float lx = 3.4e38f, ly = 3.4e38f, lz = 3.4e38f;
        float hx = -3.4e38f, hy = -3.4e38f, hz = -3.4e38f;
        for (int i = t; i < NPTS; i += FPS_T) {
            float x = bx[3 * i], y = bx[3 * i + 1], z = bx[3 * i + 2];
            lx = fminf(lx, x); hx = fmaxf(hx, x);
            ly = fminf(ly, y); hy = fmaxf(hy, y);
            lz = fminf(lz, z); hz = fmaxf(hz, z);
        }
#pragma unroll
        for (int off = 16; off; off >>= 1) {
            lx = fminf(lx, __shfl_xor_sync(~0u, lx, off));
            ly = fminf(ly, __shfl_xor_sync(~0u, ly, off));
            lz = fminf(lz, __shfl_xor_sync(~0u, lz, off));
            hx = fmaxf(hx, __shfl_xor_sync(~0u, hx, off));
            hy = fmaxf(hy, __shfl_xor_sync(~0u, hy, off));
            hz = fmaxf(hz, __shfl_xor_sync(~0u, hz, off));
        }
        if (lane == 0) {
            blox[wid] = lx; bloy[wid] = ly; bloz[wid] = lz;
            bhix[wid] = hx; bhiy[wid] = hy; bhiz[wid] = hz;
        }
        if (t < 512) cellCnt[t] = 0;
        if (t == 0) { *gnB = 0; *gnAct = 0; }
    }
    __syncthreads();
    // ---- P1: final bbox + scales ----
    if (t == 0) {
        float lx = blox[0], ly = bloy[0], lz = bloz[0];
        float hx = bhix[0], hy = bhiy[0], hz = bhiz[0];
        for (int w = 1; w < 16; w++) {
            lx = fminf(lx, blox[w]); ly = fminf(ly, bloy[w]); lz = fminf(lz, bloz[w]);
            hx = fmaxf(hx, bhix[w]); hy = fmaxf(hy, bhiy[w]); hz = fmaxf(hz, bhiz[w]);
        }
        gbb[0] = lx; gbb[1] = ly; gbb[2] = lz;
        gbb[3] = (hx > lx) ? 7.9999f / (hx - lx) : 0.0f;
        gbb[4] = (hy > ly) ? 7.9999f / (hy - ly) : 0.0f;
        gbb[5] = (hz > lz) ? 7.9999f / (hz - lz) : 0.0f;
    }
    __syncthreads();
    const float lox = gbb[0], loy = gbb[1], loz = gbb[2];
    const float scx = gbb[3], scy = gbb[4], scz = gbb[5];
    // ---- P2: histogram ----
    for (int i = t; i < NPTS; i += FPS_T) {
        float x = bx[3 * i], y = bx[3 * i + 1], z = bx[3 * i + 2];
        int qx = (int)((x - lox) * scx); qx = qx < 0 ? 0 : (qx > 7 ? 7 : qx);
        int qy = (int)((y - loy) * scy); qy = qy < 0 ? 0 : (qy > 7 ? 7 : qy);
        int qz = (int)((z - loz) * scz); qz = qz < 0 ? 0 : (qz > 7 ? 7 : qz);
        atomicAdd(&cellCnt[(qx << 6) | (qy << 3) | qz], 1);
    }
    __syncthreads();
    // ---- P3: prefix sum (warp 0) ----
    if (t < 32) {
        int base = t * 16;
        int loc[16]; int run = 0;
#pragma unroll
        for (int k = 0; k < 16; k++) { loc[k] = run; run += cellCnt[base + k]; }
        int inc = run;
#pragma unroll
        for (int off = 1; off < 32; off <<= 1) {
            int v = __shfl_up_sync(~0u, inc, off);
            if (lane >= off) inc += v;
        }
        int excl = inc - run;
#pragma unroll
        for (int k = 0; k < 16; k++) cellStart[base + k] = excl + loc[k];
    }
    __syncthreads();
    // ---- P4: re-zero counters ----
    if (t < 512) cellCnt[t] = 0;
    __syncthreads();
    // ---- P5: scatter + pd init ----
    for (int i = t; i < NPTS; i += FPS_T) {
        float x = bx[3 * i], y = bx[3 * i + 1], z = bx[3 * i + 2];
        int qx = (int)((x - lox) * scx); qx = qx < 0 ? 0 : (qx > 7 ? 7 : qx);
        int qy = (int)((y - loy) * scy); qy = qy < 0 ? 0 : (qy > 7 ? 7 : qy);
        int qz = (int)((z - loz) * scz); qz = qz < 0 ? 0 : (qz > 7 ? 7 : qz);
        int ci = (qx << 6) | (qy << 3) | qz;
        int p = cellStart[ci] + atomicAdd(&cellCnt[ci], 1);
        sxs[p] = x; sys[p] = y; szs[p] = z;
        pds[p] = 1e10f;
        opk[p] = (i << 16) | p;
    }
    __syncthreads();
    // ---- P6: build buckets (chunks of <=64) ----
    if (t < 512) {
        int cnt = cellCnt[t];
        if (cnt > 0) {
            int nch = (cnt + 63) >> 6;
            int base = atomicAdd(gnB, nch);
            int st = cellStart[t];
            for (int c = 0; c < nch; c++) {
                bstart[base + c] = st + 64 * c;
                int rem = cnt - 64 * c;
                bcnt[base + c] = rem < 64 ? rem : 64;
            }
        }
    }
    __syncthreads();
    const int nB = *gnB;
    // ---- P7: bucket bboxes + init ----
    for (int bk = t; bk < nB; bk += FPS_T) {
        int st = bstart[bk], cn = bcnt[bk];
        float lx = 3.4e38f, ly = 3.4e38f, lz = 3.4e38f;
        float hx = -3.4e38f, hy = -3.4e38f, hz = -3.4e38f;
        for (int r = 0; r < cn; r++) {
            float x = sxs[st + r], y = sys[st + r], z = szs[st + r];
            lx = fminf(lx, x); hx = fmaxf(hx, x);
            ly = fminf(ly, y); hy = fmaxf(hy, y);
            lz = fminf(lz, z); hz = fmaxf(hz, z);
        }
        blox[bk] = lx; bloy[bk] = ly; bloz[bk] = lz;
        bhix[bk] = hx; bhiy[bk] = hy; bhiz[bk] = hz;
        bmaxv[bk] = 1e10f; bpay[bk] = 0;
    }
    __syncthreads();

    // ---- main loop ----
    float cx = __ldg(bx + 0), cy = __ldg(bx + 1), cz = __ldg(bx + 2);
    if (t == 0) {
        float* o = oxyz + (size_t)b * NSAMP * 3;
        o[0] = cx; o[1] = cy; o[2] = cz;
    }
    int par = 0;

    for (int s = 1; s < NSAMP; s++) {
        const float mcx = -cx, mcy = -cy, mcz = -cz;
        const float mhxc = cx, mhyc = cy, mhzc = cz;
        // phase A: bound test + active list append
        for (int bk = t; bk < nB; bk += FPS_T) {
            float tx = fmaxf(fmaxf(__fadd_rn(blox[bk], mcx), __fadd_rn(mhxc, -bhix[bk])), 0.0f);
            float ty = fmaxf(fmaxf(__fadd_rn(bloy[bk], mcy), __fadd_rn(mhyc, -bhiy[bk])), 0.0f);
            float tz = fmaxf(fmaxf(__fadd_rn(bloz[bk], mcz), __fadd_rn(mhzc, -bhiz[bk])), 0.0f);
            float bnd = __fmul_rn(tx, tx);
            bnd = __fmaf_rn(ty, ty, bnd);
            bnd = __fmaf_rn(tz, tz, bnd);
            if (bnd < bmaxv[bk]) {
                int slot = atomicAdd(gnAct, 1);
                act[slot] = bk;
            }
        }
        __syncthreads();  // BAR1
        // phase 2: update active buckets
        const int nA = *gnAct;
        for (int ai = wid; ai < nA; ai += 16) {
            int bk = act[ai];
            int st = bstart[bk], cn = bcnt[bk];
            unsigned v = 0u; unsigned pay = 0x7fffffffu;
            int r = lane;
            if (r < cn) {
                int pos = st + r;
                float dx = __fadd_rn(sxs[pos], mcx);
                float dd = __fmul_rn(dx, dx);
                float dy = __fadd_rn(sys[pos], mcy);
                dd = __fmaf_rn(dy, dy, dd);
                float dz = __fadd_rn(szs[pos], mcz);
                dd = __fmaf_rn(dz, dz, dd);
                float nv = fminf(pds[pos], dd);
                pds[pos] = nv;
                v = __float_as_uint(nv);
                pay = (unsigned)opk[pos];
            }
            r += 32;
            if (r < cn) {
                int pos = st + r;
                float dx = __fadd_rn(sxs[pos], mcx);
                float dd = __fmul_rn(dx, dx);
                float dy = __fadd_rn(sys[pos], mcy);
                dd = __fmaf_rn(dy, dy, dd);
                float dz = __fadd_rn(szs[pos], mcz);
                dd = __fmaf_rn(dz, dz, dd);
                float nv = fminf(pds[pos], dd);
                pds[pos] = nv;
                unsigned v2 = __float_as_uint(nv);
                unsigned p2 = (unsigned)opk[pos];
                if (v2 > v || (v2 == v && p2 < pay)) { v = v2; pay = p2; }
            }
            unsigned bvw = __reduce_max_sync(0xffffffffu, v);
            unsigned mp = __reduce_min_sync(0xffffffffu, (v == bvw) ? pay : 0x7fffffffu);
            if (lane == 0) { bmaxv[bk] = __uint_as_float(bvw); bpay[bk] = (int)mp; }
        }
        __syncthreads();  // BAR2
        if (t == 0) *gnAct = 0;
        // phase 3a: per-warp partial argmax over all buckets
        unsigned v = 0u, pay = 0x7fffffffu;
        if (t < nB) { v = __float_as_uint(bmaxv[t]); pay = (unsigned)bpay[t]; }
        int e2 = t + FPS_T;
        if (e2 < nB) {
            unsigned v2 = __float_as_uint(bmaxv[e2]);
            unsigned p2 = (unsigned)bpay[e2];
            if (v2 > v || (v2 == v && p2 < pay)) { v = v2; pay = p2; }
        }
        {
            unsigned wv = __reduce_max_sync(0xffffffffu, v);
            unsigned wp = __reduce_min_sync(0xffffffffu, (v == wv) ? pay : 0x7fffffffu);
            if (lane == 0) { pv[par * 16 + wid] = wv; pp[par * 16 + wid] = (int)wp; }
        }
        __syncthreads();  // BAR3
        // phase 3b: redundant final reduce (all warps)
        unsigned v3 = 0u, p3 = 0x7fffffffu;
        if (lane < 16) { v3 = pv[par * 16 + lane]; p3 = (unsigned)pp[par * 16 + lane]; }
        unsigned gvv = __reduce_max_sync(0xffffffffu, v3);
        unsigned gpp = __reduce_min_sync(0xffffffffu, (v3 == gvv) ? p3 : 0x7fffffffu);
        int pos = (int)(gpp & 0xffffu);
        cx = sxs[pos]; cy = sys[pos]; cz = szs[pos];
        if (t == 0) {
            float* o = oxyz + ((size_t)b * NSAMP + s) * 3;
            o[0] = cx; o[1] = cy; o[2] = cz;
        }
        par ^= 1;
    }
}

// ============================================================================
// Kernel 2: KNN (k=16). Unchanged from passing version.
// ============================================================================
#define KTS 1024

__global__ __launch_bounds__(256, 1)
void knn_kernel(const float* __restrict__ xyz, const float* __restrict__ qxyz) {
    __shared__ float stx[KTS], sty[KTS], stz[KTS], st2[KTS];
    __shared__ float smd[64 * 48];
    __shared__ int smi[64 * 48];

    const int t = threadIdx.x;
    const int blk = blockIdx.x;
    const int b = blk >> 5;
    const int q0 = (blk & 31) * 64;
    const int ql = t >> 2;
    const int par = t & 3;
    const int q = q0 + ql;

    const float* qp = qxyz + ((size_t)b * NSAMP + q) * 3;
    const float qx = qp[0], qy = qp[1], qz = qp[2];
    const float q2 = qx * qx + qy * qy + qz * qz;

    float dk[16];
    int ik[16];
#pragma unroll
    for (int i = 0; i < 16; i++) { dk[i] = 3.4e38f; ik[i] = 0; }

    const float* bx = xyz + (size_t)b * NPTS * 3;
    for (int tile = 0; tile < NPTS / KTS; tile++) {
        __syncthreads();
        for (int i = t; i < KTS; i += 256) {
            int p = tile * KTS + i;
            float x = bx[p * 3 + 0], y = bx[p * 3 + 1], z = bx[p * 3 + 2];
            stx[i] = x; sty[i] = y; stz[i] = z;
            st2[i] = x * x + y * y + z * z;
        }
        __syncthreads();
        for (int j = par; j < KTS; j += 4) {
            float dot = qx * stx[j] + qy * sty[j] + qz * stz[j];
            float d = q2 + st2[j] - 2.0f * dot;
            if (d < dk[0]) {
                int idx = tile * KTS + j;
                dk[0] = d; ik[0] = idx;
#pragma unroll
                for (int r = 0; r < 15; r++) {
                    if (dk[r] < dk[r + 1]) {
                        float td = dk[r]; dk[r] = dk[r + 1]; dk[r + 1] = td;
                        int ti = ik[r]; ik[r] = ik[r + 1]; ik[r + 1] = ti;
                    }
                }
            }
        }
    }
    __syncthreads();

    if (par) {
        int base = ql * 48 + (par - 1) * 16;
#pragma unroll
        for (int i = 0; i < 16; i++) { smd[base + i] = dk[i]; smi[base + i] = ik[i]; }
    }
    __syncthreads();

    if (par == 0) {
        for (int e = 0; e < 48; e++) {
            float d = smd[ql * 48 + e];
            int idx = smi[ql * 48 + e];
            if (d < dk[0] || (d == dk[0] && idx < ik[0])) {
                dk[0] = d; ik[0] = idx;
#pragma unroll
                for (int r = 0; r < 15; r++) {
                    bool sw = (dk[r] < dk[r + 1]) ||
                              (dk[r] == dk[r + 1] && ik[r] < ik[r + 1]);
                    if (sw) {
                        float td = dk[r]; dk[r] = dk[r + 1]; dk[r + 1] = td;
                        int ti = ik[r]; ik[r] = ik[r + 1]; ik[r + 1] = ti;
                    }
                }
            }
        }
        int* dst = g_knn + (((size_t)b * NSAMP + q) << 4);
#pragma unroll
        for (int i = 0; i < 16; i++) dst[i] = ik[i];
    }
}

// ============================================================================
// Kernel 3: fused gather + MLP + maxpool + LN. Unchanged from passing version.
// ============================================================================
#define MLP_SMEM_FLOATS (8576 + 16384 + 8704 + 16896 + 2048 + 1024)
#define MLP_SMEM (MLP_SMEM_FLOATS * 4)

__global__ __launch_bounds__(256, 1)
void mlp_kernel(const float* __restrict__ xyz, const float* __restrict__ feat,
                const float* __restrict__ newxyz,
                const float* __restrict__ W1, const float* __restrict__ b1,
                const float* __restrict__ W2, const float* __restrict__ b2,
                const float* __restrict__ lg, const float* __restrict__ lb,
                float* __restrict__ outf) {
    extern __shared__ float sm[];
    float* W1s = sm;
    float* W2s = W1s + 8576;
    float* Gs  = W2s + 16384;
    float* Hs  = Gs + 8704;
    float* Ps  = Hs + 16896;
    float* Qs  = Ps + 2048;

    const int t = threadIdx.x;
    const int blk = blockIdx.x;
    const int b = blk >> 8;
    const int q0 = (blk & 255) * 8;

    for (int e = t; e < CIN * OUTDIM; e += 256) {
        int sr = e >> 7, c = e & 127;
        int dr = (sr < 3) ? (64 + sr) : (sr - 3);
        W1s[dr * 128 + c] = W1[e];
    }
    {
        const float4* src = (const float4*)W2;
        float4* dst = (float4*)W2s;
        for (int e = t; e < 4096; e += 256) dst[e] = src[e];
    }
    {
        int r = t >> 1, half = t & 1;
        int qlq = r >> 4, kk = r & 15;
        int q = q0 + qlq;
        int nidx = g_knn[(((size_t)b * NSAMP + q) << 4) + kk];
        const float* frow = feat + ((size_t)b * NPTS + nidx) * INDIM + half * 32;
        float* grow = Gs + r * 68;
#pragma unroll
        for (int i = 0; i < 8; i++) {
            float4 v = *(const float4*)(frow + i * 4);
            *(float4*)(grow + half * 32 + i * 4) = v;
        }
        if (half == 0) {
            const float* prow = xyz + ((size_t)b * NPTS + nidx) * 3;
            const float* crow = newxyz + ((size_t)b * NSAMP + q) * 3;
            grow[64] = prow[0] - crow[0];
            grow[65] = prow[1] - crow[1];
            grow[66] = prow[2] - crow[2];
        }
    }
    __syncthreads();

    const int tx = t & 15, ty = t >> 4;
    const int c0 = tx * 8, r0 = ty * 8;

    float acc[8][8];
    {
        float bb[8];
#pragma unroll
        for (int j = 0; j < 8; j++) bb[j] = __ldg(b1 + c0 + j);
#pragma unroll
        for (int i = 0; i < 8; i++)
#pragma unroll
            for (int j = 0; j < 8; j++) acc[i][j] = bb[j];
    }
    for (int k = 0; k < CIN; k++) {
        float w[8], g[8];
        float4 w0 = *(const float4*)(W1s + k * 128 + c0);
        float4 w1 = *(const float4*)(W1s + k * 128 + c0 + 4);
        w[0] = w0.x; w[1] = w0.y; w[2] = w0.z; w[3] = w0.w;
        w[4] = w1.x; w[5] = w1.y; w[6] = w1.z; w[7] = w1.w;
#pragma unroll
        for (int i = 0; i < 8; i++) g[i] = Gs[(r0 + i) * 68 + k];
#pragma unroll
        for (int i = 0; i < 8; i++)
#pragma unroll
            for (int j = 0; j < 8; j++) acc[i][j] += g[i] * w[j];
    }
#pragma unroll
    for (int i = 0; i < 8; i++) {
        float4 v0, v1;
        v0.x = fmaxf(acc[i][0], 0.f); v0.y = fmaxf(acc[i][1], 0.f);
        v0.z = fmaxf(acc[i][2], 0.f); v0.w = fmaxf(acc[i][3], 0.f);
        v1.x = fmaxf(acc[i][4], 0.f); v1.y = fmaxf(acc[i][5], 0.f);
        v1.z = fmaxf(acc[i][6], 0.f); v1.w = fmaxf(acc[i][7], 0.f);
        *(float4*)(Hs + (r0 + i) * 132 + c0) = v0;
        *(float4*)(Hs + (r0 + i) * 132 + c0 + 4) = v1;
    }
    __syncthreads();

    {
        float bb[8];
#pragma unroll
        for (int j = 0; j < 8; j++) bb[j] = __ldg(b2 + c0 + j);
#pragma unroll
        for (int i = 0; i < 8; i++)
#pragma unroll
            for (int j = 0; j < 8; j++) acc[i][j] = bb[j];
    }
    for (int k = 0; k < OUTDIM; k++) {
        float w[8], h[8];
        float4 w0 = *(const float4*)(W2s + k * 128 + c0);
        float4 w1 = *(const float4*)(W2s + k * 128 + c0 + 4);
        w[0] = w0.x; w[1] = w0.y; w[2] = w0.z; w[3] = w0.w;
        w[4] = w1.x; w[5] = w1.y; w[6] = w1.z; w[7] = w1.w;
#pragma unroll
        for (int i = 0; i < 8; i++) h[i] = Hs[(r0 + i) * 132 + k];
#pragma unroll
        for (int i = 0; i < 8; i++)
#pragma unroll
            for (int j = 0; j < 8; j++) acc[i][j] += h[i] * w[j];
    }
    {
        float m[8];
#pragma unroll
        for (int j = 0; j < 8; j++) {
            float v = acc[0][j];
#pragma unroll
            for (int i = 1; i < 8; i++) v = fmaxf(v, acc[i][j]);
            m[j] = v;
        }
        float4 v0, v1;
        v0.x = m[0]; v0.y = m[1]; v0.z = m[2]; v0.w = m[3];
        v1.x = m[4]; v1.y = m[5]; v1.z = m[6]; v1.w = m[7];
        *(float4*)(Ps + ty * 128 + c0) = v0;
        *(float4*)(Ps + ty * 128 + c0 + 4) = v1;
    }
    __syncthreads();
    for (int e = t; e < 1024; e += 256) {
        int q = e >> 7, c = e & 127;
        Qs[e] = fmaxf(Ps[(2 * q) * 128 + c], Ps[(2 * q + 1) * 128 + c]);
    }
    __syncthreads();

    {
        int w = t >> 5, l = t & 31;
        float4 v = *(const float4*)(Qs + w * 128 + l * 4);
        float sum = v.x + v.y + v.z + v.w;
        float sq = fmaf(v.x, v.x, fmaf(v.y, v.y, fmaf(v.z, v.z, v.w * v.w)));
#pragma unroll
        for (int off = 16; off; off >>= 1) {
            sum += __shfl_xor_sync(0xffffffffu, sum, off);
            sq += __shfl_xor_sync(0xffffffffu, sq, off);
        }
        float mu = sum * (1.0f / 128.0f);
        float var = sq * (1.0f / 128.0f) - mu * mu;
        float rs = rsqrtf(var + 1e-5f);
        int qg = q0 + w;
        int c = l * 4;
        float4 o;
        o.x = (v.x - mu) * rs * __ldg(lg + c + 0) + __ldg(lb + c + 0);
        o.y = (v.y - mu) * rs * __ldg(lg + c + 1) + __ldg(lb + c + 1);
        o.z = (v.z - mu) * rs * __ldg(lg + c + 2) + __ldg(lb + c + 2);
        o.w = (v.w - mu) * rs * __ldg(lg + c + 3) + __ldg(lb + c + 3);
        *(float4*)(outf + (((size_t)b * NSAMP + qg) << 7) + c) = o;
    }
}

// ============================================================================
extern "C" void kernel_launch(void* const* d_in, const int* in_sizes, int n_in,
                              void* d_out, int out_size) {
    const float* xyz  = (const float*)d_in[0];
    const float* feat = (const float*)d_in[1];
    const float* W1   = (const float*)d_in[2];
    const float* b1   = (const float*)d_in[3];
    const float* W2   = (const float*)d_in[4];
    const float* b2   = (const float*)d_in[5];
    const float* lg   = (const float*)d_in[6];
    const float* lb   = (const float*)d_in[7];

    float* out = (float*)d_out;
    float* oxyz = out;
    float* ofeat = out + (size_t)BATCH * NSAMP * 3;

    cudaFuncSetAttribute(fps_kernel, cudaFuncAttributeMaxDynamicSharedMemorySize, FPS_SMEM);
    cudaFuncSetAttribute(mlp_kernel, cudaFuncAttributeMaxDynamicSharedMemorySize, MLP_SMEM);

    fps_kernel<<<BATCH, FPS_T, FPS_SMEM>>>(xyz, oxyz);
    knn_kernel<<<128, 256>>>(xyz, oxyz);
    mlp_kernel<<<1024, 256, MLP_SMEM>>>(xyz, feat, oxyz, W1, b1, W2, b2, lg, lb, ofeat);
}

// round 5
// speedup vs baseline: 1.4020x; 1.2563x over previous
#include <cuda_runtime.h>
#include <cuda_bf16.h>
#include <cstdint>

#define BATCH 4
#define NPTS 8192
#define NSAMP 2048
#define KNN_K 16
#define INDIM 64
#define OUTDIM 128
#define CIN 67

__device__ int g_knn[BATCH * NSAMP * KNN_K];

// ============================================================================
// Kernel 1: farthest point sampling. One block per batch, 512 threads.
// Points Morton/cell counting-sorted; each thread owns 16 contiguous sorted
// points ENTIRELY IN REGISTERS (coords, min-dists, payloads, slice bbox,
// running max). Per iteration: register bound test -> optional 16-pt register
// rescan -> single-barrier two-level REDUX argmax.
// ============================================================================
#define FPS_T 512
// floats: 3*8192 coords; ints: 8192 sorig + 1024 cells; 64 partials; misc
#define FPS_SMEM ((3 * NPTS + NPTS + 1024 + 64 + 112 + 16) * 4)

__device__ __forceinline__ int spread3(int v) {
    return (v & 1) | ((v & 2) << 2) | ((v & 4) << 4);
}

__global__ __launch_bounds__(FPS_T, 1)
void fps_kernel(const float* __restrict__ xyz, float* __restrict__ oxyz) {
    extern __shared__ float sm[];
    float* sxs = sm;
    float* sys = sxs + NPTS;
    float* szs = sys + NPTS;
    int* sorig = (int*)(szs + NPTS);
    int* cellCnt = sorig + NPTS;            // 512
    int* cellStart = cellCnt + 512;         // 512
    unsigned* pv = (unsigned*)(cellStart + 512);  // 2x16
    unsigned* pp = pv + 32;                       // 2x16
    float* wred = (float*)(pp + 32);        // 16 warps x 6 bbox partials + 6
    int* gpos0 = (int*)(wred + 102);

    const int b = blockIdx.x;
    const int t = threadIdx.x;
    const int wid = t >> 5;
    const int lane = t & 31;
    const float* bx = xyz + (size_t)b * NPTS * 3;

    // ---- cloud bbox ----
    {
        float lx = 3.4e38f, ly = 3.4e38f, lz = 3.4e38f;
        float hx = -3.4e38f, hy = -3.4e38f, hz = -3.4e38f;
        for (int i = t; i < NPTS; i += FPS_T) {
            float x = bx[3 * i], y = bx[3 * i + 1], z = bx[3 * i + 2];
            lx = fminf(lx, x); hx = fmaxf(hx, x);
            ly = fminf(ly, y); hy = fmaxf(hy, y);
            lz = fminf(lz, z); hz = fmaxf(hz, z);
        }
#pragma unroll
        for (int off = 16; off; off >>= 1) {
            lx = fminf(lx, __shfl_xor_sync(~0u, lx, off));
            ly = fminf(ly, __shfl_xor_sync(~0u, ly, off));
            lz = fminf(lz, __shfl_xor_sync(~0u, lz, off));
            hx = fmaxf(hx, __shfl_xor_sync(~0u, hx, off));
            hy = fmaxf(hy, __shfl_xor_sync(~0u, hy, off));
            hz = fmaxf(hz, __shfl_xor_sync(~0u, hz, off));
        }
        if (lane == 0) {
            wred[wid * 6 + 0] = lx; wred[wid * 6 + 1] = ly; wred[wid * 6 + 2] = lz;
            wred[wid * 6 + 3] = hx; wred[wid * 6 + 4] = hy; wred[wid * 6 + 5] = hz;
        }
        if (t < 512) cellCnt[t] = 0;
    }
    __syncthreads();
    if (t == 0) {
        float lx = wred[0], ly = wred[1], lz = wred[2];
        float hx = wred[3], hy = wred[4], hz = wred[5];
        for (int w = 1; w < 16; w++) {
            lx = fminf(lx, wred[w * 6 + 0]); ly = fminf(ly, wred[w * 6 + 1]);
            lz = fminf(lz, wred[w * 6 + 2]);
            hx = fmaxf(hx, wred[w * 6 + 3]); hy = fmaxf(hy, wred[w * 6 + 4]);
            hz = fmaxf(hz, wred[w * 6 + 5]);
        }
        wred[96] = lx; wred[97] = ly; wred[98] = lz;
        wred[99]  = (hx > lx) ? 7.9999f / (hx - lx) : 0.0f;
        wred[100] = (hy > ly) ? 7.9999f / (hy - ly) : 0.0f;
        wred[101] = (hz > lz) ? 7.9999f / (hz - lz) : 0.0f;
    }
    __syncthreads();
    const float lox = wred[96], loy = wred[97], loz = wred[98];
    const float scx = wred[99], scy = wred[100], scz = wred[101];
    // ---- histogram (Morton cell ids) ----
    for (int i = t; i < NPTS; i += FPS_T) {
        float x = bx[3 * i], y = bx[3 * i + 1], z = bx[3 * i + 2];
        int qx = (int)((x - lox) * scx); qx = qx < 0 ? 0 : (qx > 7 ? 7 : qx);
        int qy = (int)((y - loy) * scy); qy = qy < 0 ? 0 : (qy > 7 ? 7 : qy);
        int qz = (int)((z - loz) * scz); qz = qz < 0 ? 0 : (qz > 7 ? 7 : qz);
        int ci = (spread3(qx) << 2) | (spread3(qy) << 1) | spread3(qz);
        atomicAdd(&cellCnt[ci], 1);
    }
    __syncthreads();
    // ---- prefix sum (warp 0) ----
    if (t < 32) {
        int base = t * 16;
        int loc[16]; int run = 0;
#pragma unroll
        for (int k = 0; k < 16; k++) { loc[k] = run; run += cellCnt[base + k]; }
        int inc = run;
#pragma unroll
        for (int off = 1; off < 32; off <<= 1) {
            int v = __shfl_up_sync(~0u, inc, off);
            if (lane >= off) inc += v;
        }
        int excl = inc - run;
#pragma unroll
        for (int k = 0; k < 16; k++) cellStart[base + k] = excl + loc[k];
    }
    __syncthreads();
    if (t < 512) cellCnt[t] = 0;
    __syncthreads();
    // ---- scatter ----
    for (int i = t; i < NPTS; i += FPS_T) {
        float x = bx[3 * i], y = bx[3 * i + 1], z = bx[3 * i + 2];
        int qx = (int)((x - lox) * scx); qx = qx < 0 ? 0 : (qx > 7 ? 7 : qx);
        int qy = (int)((y - loy) * scy); qy = qy < 0 ? 0 : (qy > 7 ? 7 : qy);
        int qz = (int)((z - loz) * scz); qz = qz < 0 ? 0 : (qz > 7 ? 7 : qz);
        int ci = (spread3(qx) << 2) | (spread3(qy) << 1) | spread3(qz);
        int p = cellStart[ci] + atomicAdd(&cellCnt[ci], 1);
        sxs[p] = x; sys[p] = y; szs[p] = z;
        sorig[p] = i;
    }
    __syncthreads();

    // ---- load this thread's 16-point slice into registers ----
    const int base = t * 16;
    float px[16], py[16], pz[16], pd[16];
    int pay[16];
    float blx = 3.4e38f, bly = 3.4e38f, blz = 3.4e38f;
    float bhx = -3.4e38f, bhy = -3.4e38f, bhz = -3.4e38f;
#pragma unroll
    for (int i = 0; i < 16; i++) {
        int pos = base + i;
        float x = sxs[pos], y = sys[pos], z = szs[pos];
        px[i] = x; py[i] = y; pz[i] = z;
        pd[i] = 1e10f;
        int og = sorig[pos];
        pay[i] = (og << 13) | pos;
        if (og == 0) *gpos0 = pos;
        blx = fminf(blx, x); bhx = fmaxf(bhx, x);
        bly = fminf(bly, y); bhy = fmaxf(bhy, y);
        blz = fminf(blz, z); bhz = fmaxf(bhz, z);
    }
    // initial thread max (all pd equal -> min payload)
    unsigned bmaxv; int bpay;
    {
        unsigned bv = 0u; int bp = 0x7fffffff;
#pragma unroll
        for (int i = 0; i < 16; i++) {
            unsigned v = __float_as_uint(pd[i]);
            if (v > bv || (v == bv && pay[i] < bp)) { bv = v; bp = pay[i]; }
        }
        bmaxv = bv; bpay = bp;
    }
    __syncthreads();

    // first centroid = original index 0
    float cx, cy, cz;
    {
        int p0 = *gpos0;
        cx = sxs[p0]; cy = sys[p0]; cz = szs[p0];
        if (t == 0) {
            float* o = oxyz + (size_t)b * NSAMP * 3;
            o[0] = cx; o[1] = cy; o[2] = cz;
        }
    }

    int par = 0;
    for (int s = 1; s < NSAMP; s++) {
        const float mcx = -cx, mcy = -cy, mcz = -cz;
        // bound test (bit-exact monotone lower bound vs register stale max)
        float tx = fmaxf(fmaxf(__fadd_rn(blx, mcx), __fadd_rn(cx, -bhx)), 0.0f);
        float ty = fmaxf(fmaxf(__fadd_rn(bly, mcy), __fadd_rn(cy, -bhy)), 0.0f);
        float tz = fmaxf(fmaxf(__fadd_rn(blz, mcz), __fadd_rn(cz, -bhz)), 0.0f);
        float bnd = __fmul_rn(tx, tx);
        bnd = __fmaf_rn(ty, ty, bnd);
        bnd = __fmaf_rn(tz, tz, bnd);
        if (bnd < __uint_as_float(bmaxv)) {
#pragma unroll
            for (int i = 0; i < 16; i++) {
                float dx = __fadd_rn(px[i], mcx);
                float dd = __fmul_rn(dx, dx);
                float dy = __fadd_rn(py[i], mcy);
                dd = __fmaf_rn(dy, dy, dd);
                float dz = __fadd_rn(pz[i], mcz);
                dd = __fmaf_rn(dz, dz, dd);
                pd[i] = fminf(pd[i], dd);
            }
            unsigned bv = 0u; int bp = 0x7fffffff;
#pragma unroll
            for (int i = 0; i < 16; i++) {
                unsigned v = __float_as_uint(pd[i]);
                if (v > bv || (v == bv && pay[i] < bp)) { bv = v; bp = pay[i]; }
            }
            bmaxv = bv; bpay = bp;
        }
        // two-level argmax (value-bits max, then min payload)
        unsigned wv = __reduce_max_sync(0xffffffffu, bmaxv);
        unsigned wp = __reduce_min_sync(0xffffffffu,
                                        (bmaxv == wv) ? (unsigned)bpay : 0x7fffffffu);
        if (lane == 0) { pv[par * 16 + wid] = wv; pp[par * 16 + wid] = wp; }
        __syncthreads();
        unsigned v3 = (lane < 16) ? pv[par * 16 + lane] : 0u;
        unsigned p3 = (lane < 16) ? pp[par * 16 + lane] : 0x7fffffffu;
        unsigned gv = __reduce_max_sync(0xffffffffu, v3);
        unsigned gp = __reduce_min_sync(0xffffffffu, (v3 == gv) ? p3 : 0x7fffffffu);
        int pos = (int)(gp & 0x1fffu);
        cx = sxs[pos]; cy = sys[pos]; cz = szs[pos];
        if (t == 0) {
            float* o = oxyz + ((size_t)b * NSAMP + s) * 3;
            o[0] = cx; o[1] = cy; o[2] = cz;
        }
        par ^= 1;
    }
}

// ============================================================================
// Kernel 2: KNN (k=16). Unchanged from passing version.
// ============================================================================
#define KTS 1024

__global__ __launch_bounds__(256, 1)
void knn_kernel(const float* __restrict__ xyz, const float* __restrict__ qxyz) {
    __shared__ float stx[KTS], sty[KTS], stz[KTS], st2[KTS];
    __shared__ float smd[64 * 48];
    __shared__ int smi[64 * 48];

    const int t = threadIdx.x;
    const int blk = blockIdx.x;
    const int b = blk >> 5;
    const int q0 = (blk & 31) * 64;
    const int ql = t >> 2;
    const int par = t & 3;
    const int q = q0 + ql;

    const float* qp = qxyz + ((size_t)b * NSAMP + q) * 3;
    const float qx = qp[0], qy = qp[1], qz = qp[2];
    const float q2 = qx * qx + qy * qy + qz * qz;

    float dk[16];
    int ik[16];
#pragma unroll
    for (int i = 0; i < 16; i++) { dk[i] = 3.4e38f; ik[i] = 0; }

    const float* bx = xyz + (size_t)b * NPTS * 3;
    for (int tile = 0; tile < NPTS / KTS; tile++) {
        __syncthreads();
        for (int i = t; i < KTS; i += 256) {
            int p = tile * KTS + i;
            float x = bx[p * 3 + 0], y = bx[p * 3 + 1], z = bx[p * 3 + 2];
            stx[i] = x; sty[i] = y; stz[i] = z;
            st2[i] = x * x + y * y + z * z;
        }
        __syncthreads();
        for (int j = par; j < KTS; j += 4) {
            float dot = qx * stx[j] + qy * sty[j] + qz * stz[j];
            float d = q2 + st2[j] - 2.0f * dot;
            if (d < dk[0]) {
                int idx = tile * KTS + j;
                dk[0] = d; ik[0] = idx;
#pragma unroll
                for (int r = 0; r < 15; r++) {
                    if (dk[r] < dk[r + 1]) {
                        float td = dk[r]; dk[r] = dk[r + 1]; dk[r + 1] = td;
                        int ti = ik[r]; ik[r] = ik[r + 1]; ik[r + 1] = ti;
                    }
                }
            }
        }
    }
    __syncthreads();

    if (par) {
        int basee = ql * 48 + (par - 1) * 16;
#pragma unroll
        for (int i = 0; i < 16; i++) { smd[basee + i] = dk[i]; smi[basee + i] = ik[i]; }
    }
    __syncthreads();

    if (par == 0) {
        for (int e = 0; e < 48; e++) {
            float d = smd[ql * 48 + e];
            int idx = smi[ql * 48 + e];
            if (d < dk[0] || (d == dk[0] && idx < ik[0])) {
                dk[0] = d; ik[0] = idx;
#pragma unroll
                for (int r = 0; r < 15; r++) {
                    bool sw = (dk[r] < dk[r + 1]) ||
                              (dk[r] == dk[r + 1] && ik[r] < ik[r + 1]);
                    if (sw) {
                        float td = dk[r]; dk[r] = dk[r + 1]; dk[r + 1] = td;
                        int ti = ik[r]; ik[r] = ik[r + 1]; ik[r + 1] = ti;
                    }
                }
            }
        }
        int* dst = g_knn + (((size_t)b * NSAMP + q) << 4);
#pragma unroll
        for (int i = 0; i < 16; i++) dst[i] = ik[i];
    }
}

// ============================================================================
// Kernel 3: fused gather + MLP + maxpool + LN. Unchanged from passing version.
// ============================================================================
#define MLP_SMEM_FLOATS (8576 + 16384 + 8704 + 16896 + 2048 + 1024)
#define MLP_SMEM (MLP_SMEM_FLOATS * 4)

__global__ __launch_bounds__(256, 1)
void mlp_kernel(const float* __restrict__ xyz, const float* __restrict__ feat,
                const float* __restrict__ newxyz,
                const float* __restrict__ W1, const float* __restrict__ b1,
                const float* __restrict__ W2, const float* __restrict__ b2,
                const float* __restrict__ lg, const float* __restrict__ lb,
                float* __restrict__ outf) {
    extern __shared__ float sm[];
    float* W1s = sm;
    float* W2s = W1s + 8576;
    float* Gs  = W2s + 16384;
    float* Hs  = Gs + 8704;
    float* Ps  = Hs + 16896;
    float* Qs  = Ps + 2048;

    const int t = threadIdx.x;
    const int blk = blockIdx.x;
    const int b = blk >> 8;
    const int q0 = (blk & 255) * 8;

    for (int e = t; e < CIN * OUTDIM; e += 256) {
        int sr = e >> 7, c = e & 127;
        int dr = (sr < 3) ? (64 + sr) : (sr - 3);
        W1s[dr * 128 + c] = W1[e];
    }
    {
        const float4* src = (const float4*)W2;
        float4* dst = (float4*)W2s;
        for (int e = t; e < 4096; e += 256) dst[e] = src[e];
    }
    {
        int r = t >> 1, half = t & 1;
        int qlq = r >> 4, kk = r & 15;
        int q = q0 + qlq;
        int nidx = g_knn[(((size_t)b * NSAMP + q) << 4) + kk];
        const float* frow = feat + ((size_t)b * NPTS + nidx) * INDIM + half * 32;
        float* grow = Gs + r * 68;
#pragma unroll
        for (int i = 0; i < 8; i++) {
            float4 v = *(const float4*)(frow + i * 4);
            *(float4*)(grow + half * 32 + i * 4) = v;
        }
        if (half == 0) {
            const float* prow = xyz + ((size_t)b * NPTS + nidx) * 3;
            const float* crow = newxyz + ((size_t)b * NSAMP + q) * 3;
            grow[64] = prow[0] - crow[0];
            grow[65] = prow[1] - crow[1];
            grow[66] = prow[2] - crow[2];
        }
    }
    __syncthreads();

    const int tx = t & 15, ty = t >> 4;
    const int c0 = tx * 8, r0 = ty * 8;

    float acc[8][8];
    {
        float bb[8];
#pragma unroll
        for (int j = 0; j < 8; j++) bb[j] = __ldg(b1 + c0 + j);
#pragma unroll
        for (int i = 0; i < 8; i++)
#pragma unroll
            for (int j = 0; j < 8; j++) acc[i][j] = bb[j];
    }
    for (int k = 0; k < CIN; k++) {
        float w[8], g[8];
        float4 w0 = *(const float4*)(W1s + k * 128 + c0);
        float4 w1 = *(const float4*)(W1s + k * 128 + c0 + 4);
        w[0] = w0.x; w[1] = w0.y; w[2] = w0.z; w[3] = w0.w;
        w[4] = w1.x; w[5] = w1.y; w[6] = w1.z; w[7] = w1.w;
#pragma unroll
        for (int i = 0; i < 8; i++) g[i] = Gs[(r0 + i) * 68 + k];
#pragma unroll
        for (int i = 0; i < 8; i++)
#pragma unroll
            for (int j = 0; j < 8; j++) acc[i][j] += g[i] * w[j];
    }
#pragma unroll
    for (int i = 0; i < 8; i++) {
        float4 v0, v1;
        v0.x = fmaxf(acc[i][0], 0.f); v0.y = fmaxf(acc[i][1], 0.f);
        v0.z = fmaxf(acc[i][2], 0.f); v0.w = fmaxf(acc[i][3], 0.f);
        v1.x = fmaxf(acc[i][4], 0.f); v1.y = fmaxf(acc[i][5], 0.f);
        v1.z = fmaxf(acc[i][6], 0.f); v1.w = fmaxf(acc[i][7], 0.f);
        *(float4*)(Hs + (r0 + i) * 132 + c0) = v0;
        *(float4*)(Hs + (r0 + i) * 132 + c0 + 4) = v1;
    }
    __syncthreads();

    {
        float bb[8];
#pragma unroll
        for (int j = 0; j < 8; j++) bb[j] = __ldg(b2 + c0 + j);
#pragma unroll
        for (int i = 0; i < 8; i++)
#pragma unroll
            for (int j = 0; j < 8; j++) acc[i][j] = bb[j];
    }
    for (int k = 0; k < OUTDIM; k++) {
        float w[8], h[8];
        float4 w0 = *(const float4*)(W2s + k * 128 + c0);
        float4 w1 = *(const float4*)(W2s + k * 128 + c0 + 4);
        w[0] = w0.x; w[1] = w0.y; w[2] = w0.z; w[3] = w0.w;
        w[4] = w1.x; w[5] = w1.y; w[6] = w1.z; w[7] = w1.w;
#pragma unroll
        for (int i = 0; i < 8; i++) h[i] = Hs[(r0 + i) * 132 + k];
#pragma unroll
        for (int i = 0; i < 8; i++)
#pragma unroll
            for (int j = 0; j < 8; j++) acc[i][j] += h[i] * w[j];
    }
    {
        float m[8];
#pragma unroll
        for (int j = 0; j < 8; j++) {
            float v = acc[0][j];
#pragma unroll
            for (int i = 1; i < 8; i++) v = fmaxf(v, acc[i][j]);
            m[j] = v;
        }
        float4 v0, v1;
        v0.x = m[0]; v0.y = m[1]; v0.z = m[2]; v0.w = m[3];
        v1.x = m[4]; v1.y = m[5]; v1.z = m[6]; v1.w = m[7];
        *(float4*)(Ps + ty * 128 + c0) = v0;
        *(float4*)(Ps + ty * 128 + c0 + 4) = v1;
    }
    __syncthreads();
    for (int e = t; e < 1024; e += 256) {
        int q = e >> 7, c = e & 127;
        Qs[e] = fmaxf(Ps[(2 * q) * 128 + c], Ps[(2 * q + 1) * 128 + c]);
    }
    __syncthreads();

    {
        int w = t >> 5, l = t & 31;
        float4 v = *(const float4*)(Qs + w * 128 + l * 4);
        float sum = v.x + v.y + v.z + v.w;
        float sq = fmaf(v.x, v.x, fmaf(v.y, v.y, fmaf(v.z, v.z, v.w * v.w)));
#pragma unroll
        for (int off = 16; off; off >>= 1) {
            sum += __shfl_xor_sync(0xffffffffu, sum, off);
            sq += __shfl_xor_sync(0xffffffffu, sq, off);
        }
        float mu = sum * (1.0f / 128.0f);
        float var = sq * (1.0f / 128.0f) - mu * mu;
        float rs = rsqrtf(var + 1e-5f);
        int qg = q0 + w;
        int c = l * 4;
        float4 o;
        o.x = (v.x - mu) * rs * __ldg(lg + c + 0) + __ldg(lb + c + 0);
        o.y = (v.y - mu) * rs * __ldg(lg + c + 1) + __ldg(lb + c + 1);
        o.z = (v.z - mu) * rs * __ldg(lg + c + 2) + __ldg(lb + c + 2);
        o.w = (v.w - mu) * rs * __ldg(lg + c + 3) + __ldg(lb + c + 3);
        *(float4*)(outf + (((size_t)b * NSAMP + qg) << 7) + c) = o;
    }
}

// ============================================================================
extern "C" void kernel_launch(void* const* d_in, const int* in_sizes, int n_in,
                              void* d_out, int out_size) {
    const float* xyz  = (const float*)d_in[0];
    const float* feat = (const float*)d_in[1];
    const float* W1   = (const float*)d_in[2];
    const float* b1   = (const float*)d_in[3];
    const float* W2   = (const float*)d_in[4];
    const float* b2   = (const float*)d_in[5];
    const float* lg   = (const float*)d_in[6];
    const float* lb   = (const float*)d_in[7];

    float* out = (float*)d_out;
    float* oxyz = out;
    float* ofeat = out + (size_t)BATCH * NSAMP * 3;

    cudaFuncSetAttribute(fps_kernel, cudaFuncAttributeMaxDynamicSharedMemorySize, FPS_SMEM);
    cudaFuncSetAttribute(mlp_kernel, cudaFuncAttributeMaxDynamicSharedMemorySize, MLP_SMEM);

    fps_kernel<<<BATCH, FPS_T, FPS_SMEM>>>(xyz, oxyz);
    knn_kernel<<<128, 256>>>(xyz, oxyz);
    mlp_kernel<<<1024, 256, MLP_SMEM>>>(xyz, feat, oxyz, W1, b1, W2, b2, lg, lb, ofeat);
}